// round 2
// baseline (speedup 1.0000x reference)
#include <cuda_runtime.h>

#define NRES 384
#define CH 128
#define NN (NRES*NRES)
#define EPSF 1e-5f

// ---- scratch (device globals; no allocation) ----
__device__ float g_at[CH*NN];     // a transposed [h][i*384+k]
__device__ float g_bt[CH*NN];     // b transposed [h][j*384+k]
__device__ float g_gate[NN*CH];   // sigmoid gate, row-major
__device__ float g_xt[CH*NN];     // triangle out [h][i*384+j]
__device__ float g_wT[6*CH*CH];   // transposed weights

__device__ __forceinline__ float sigf(float x){ return 1.f/(1.f+__expf(-x)); }

// ---- 128x128 transpose into g_wT[idx] ----
__global__ void transpose128(const float* __restrict__ src, int idx){
    __shared__ float t[32][33];
    float* dst = g_wT + idx*CH*CH;
    int x0=blockIdx.x*32, y0=blockIdx.y*32;
    int tx=threadIdx.x, ty=threadIdx.y;
    #pragma unroll
    for (int j=0;j<32;j+=8) t[ty+j][tx] = src[(y0+ty+j)*CH + x0+tx];
    __syncthreads();
    #pragma unroll
    for (int j=0;j<32;j+=8) dst[(x0+ty+j)*CH + y0+tx] = t[tx][ty+j];
}

// ---- fused LN + 5 GEMMs + gated epilogues; 32 rows/block ----
__global__ __launch_bounds__(256)
void proj_kernel(const float* __restrict__ z, const float* __restrict__ mask,
                 const float* __restrict__ lnw, const float* __restrict__ lnb,
                 const float* __restrict__ agb, const float* __restrict__ apb,
                 const float* __restrict__ bgb, const float* __restrict__ bpb,
                 const float* __restrict__ gb)
{
    __shared__ float z_s[32*132];
    __shared__ float wg_s[8*132];
    __shared__ float wp_s[8*132];
    __shared__ float ot[128*34];
    int tid = threadIdx.x;
    int row0 = blockIdx.x*32;

    const float4* z4 = (const float4*)(z + (size_t)row0*CH);
    #pragma unroll
    for (int it=0; it<4; ++it){
        int f = tid + it*256;
        int r = f>>5, c4 = f&31;
        *(float4*)(z_s + r*132 + c4*4) = z4[f];
    }
    __syncthreads();

    int lane = tid&31, wid = tid>>5;
    #pragma unroll
    for (int rr=0; rr<4; ++rr){
        int r = wid*4+rr;
        float v[4], s=0.f, q=0.f;
        #pragma unroll
        for (int m=0;m<4;++m){ float x=z_s[r*132+lane+32*m]; v[m]=x; s+=x; q+=x*x; }
        #pragma unroll
        for (int o=16;o>0;o>>=1){ s+=__shfl_xor_sync(0xffffffffu,s,o); q+=__shfl_xor_sync(0xffffffffu,q,o); }
        float mu=s*(1.f/128.f), var=q*(1.f/128.f)-mu*mu;
        float rs=rsqrtf(fmaxf(var,0.f)+EPSF);
        #pragma unroll
        for (int m=0;m<4;++m){
            int c=lane+32*m;
            z_s[r*132+c] = (v[m]-mu)*rs*lnw[c]+lnb[c];
        }
    }
    __syncthreads();

    int tx = tid&15, ty = tid>>4;
    const float* WgT[3] = {g_wT, g_wT+2*CH*CH, g_wT+4*CH*CH};
    const float* WpT[3] = {g_wT+CH*CH, g_wT+3*CH*CH, 0};
    const float* GB[3]  = {agb, bgb, gb};
    const float* PB[3]  = {apb, bpb, 0};

    for (int ph=0; ph<3; ++ph){
        bool hasP = (ph<2);
        float accg[2][8], accp[2][8];
        #pragma unroll
        for (int u=0;u<2;++u)
            #pragma unroll
            for (int v=0;v<8;++v){ accg[u][v]=0.f; accp[u][v]=0.f; }

        for (int c0=0;c0<CH;c0+=8){
            int c=tid>>5, o4=tid&31;
            *(float4*)(wg_s + c*132 + o4*4) = *(const float4*)(WgT[ph] + (c0+c)*CH + o4*4);
            if (hasP)
                *(float4*)(wp_s + c*132 + o4*4) = *(const float4*)(WpT[ph] + (c0+c)*CH + o4*4);
            __syncthreads();
            #pragma unroll
            for (int i=0;i<8;++i){
                float z0 = z_s[(ty*2+0)*132 + c0+i];
                float z1 = z_s[(ty*2+1)*132 + c0+i];
                float4 wa = *(float4*)(wg_s + i*132 + tx*8);
                float4 wb = *(float4*)(wg_s + i*132 + tx*8 + 4);
                accg[0][0]+=z0*wa.x; accg[0][1]+=z0*wa.y; accg[0][2]+=z0*wa.z; accg[0][3]+=z0*wa.w;
                accg[0][4]+=z0*wb.x; accg[0][5]+=z0*wb.y; accg[0][6]+=z0*wb.z; accg[0][7]+=z0*wb.w;
                accg[1][0]+=z1*wa.x; accg[1][1]+=z1*wa.y; accg[1][2]+=z1*wa.z; accg[1][3]+=z1*wa.w;
                accg[1][4]+=z1*wb.x; accg[1][5]+=z1*wb.y; accg[1][6]+=z1*wb.z; accg[1][7]+=z1*wb.w;
                if (hasP){
                    float4 pa = *(float4*)(wp_s + i*132 + tx*8);
                    float4 pb4= *(float4*)(wp_s + i*132 + tx*8 + 4);
                    accp[0][0]+=z0*pa.x; accp[0][1]+=z0*pa.y; accp[0][2]+=z0*pa.z; accp[0][3]+=z0*pa.w;
                    accp[0][4]+=z0*pb4.x; accp[0][5]+=z0*pb4.y; accp[0][6]+=z0*pb4.z; accp[0][7]+=z0*pb4.w;
                    accp[1][0]+=z1*pa.x; accp[1][1]+=z1*pa.y; accp[1][2]+=z1*pa.z; accp[1][3]+=z1*pa.w;
                    accp[1][4]+=z1*pb4.x; accp[1][5]+=z1*pb4.y; accp[1][6]+=z1*pb4.z; accp[1][7]+=z1*pb4.w;
                }
            }
            __syncthreads();
        }

        if (hasP){
            float* dstT = ph ? g_bt : g_at;
            #pragma unroll
            for (int u=0;u<2;++u){
                int r = ty*2+u;
                float mk = mask[row0+r];
                #pragma unroll
                for (int v=0;v<8;++v){
                    int o = tx*8+v;
                    ot[o*34 + r] = mk * sigf(accg[u][v]+GB[ph][o]) * (accp[u][v]+PB[ph][o]);
                }
            }
            __syncthreads();
            #pragma unroll
            for (int it=0; it<16; ++it){
                int f = tid + it*256;
                int r=f&31, o=f>>5;
                dstT[(size_t)o*NN + row0 + r] = ot[o*34+r];
            }
            __syncthreads();
        } else {
            #pragma unroll
            for (int u=0;u<2;++u){
                int grow = row0 + ty*2+u;
                #pragma unroll
                for (int v=0;v<8;++v){
                    int o=tx*8+v;
                    g_gate[(size_t)grow*CH + o] = sigf(accg[u][v]+gb[o]);
                }
            }
        }
    }
}

// ---- per-channel triangle GEMM: X_h = A_h @ B_h^T ----
__global__ __launch_bounds__(256)
void tri_kernel(){
    __shared__ float At[16*132], Bt[16*132];
    int h = blockIdx.z;
    int i0 = blockIdx.y*128, j0 = blockIdx.x*128;
    const float* A = g_at + (size_t)h*NN;
    const float* B = g_bt + (size_t)h*NN;
    int tid=threadIdx.x, tx=tid&15, ty=tid>>4;
    float acc[8][8];
    #pragma unroll
    for (int r=0;r<8;++r)
        #pragma unroll
        for (int c=0;c<8;++c) acc[r][c]=0.f;

    for (int k0=0;k0<NRES;k0+=16){
        #pragma unroll
        for (int it=0; it<2; ++it){
            int f = tid + it*256;
            int i = f>>2, k4 = (f&3)*4;
            float4 va = *(const float4*)(A + (size_t)(i0+i)*NRES + k0 + k4);
            At[(k4+0)*132+i]=va.x; At[(k4+1)*132+i]=va.y; At[(k4+2)*132+i]=va.z; At[(k4+3)*132+i]=va.w;
            float4 vb = *(const float4*)(B + (size_t)(j0+i)*NRES + k0 + k4);
            Bt[(k4+0)*132+i]=vb.x; Bt[(k4+1)*132+i]=vb.y; Bt[(k4+2)*132+i]=vb.z; Bt[(k4+3)*132+i]=vb.w;
        }
        __syncthreads();
        #pragma unroll
        for (int kk=0;kk<16;++kk){
            float a[8], b[8];
            *(float4*)(a)   = *(float4*)(At + kk*132 + ty*8);
            *(float4*)(a+4) = *(float4*)(At + kk*132 + ty*8 + 4);
            *(float4*)(b)   = *(float4*)(Bt + kk*132 + tx*8);
            *(float4*)(b+4) = *(float4*)(Bt + kk*132 + tx*8 + 4);
            #pragma unroll
            for (int r=0;r<8;++r)
                #pragma unroll
                for (int c=0;c<8;++c) acc[r][c] += a[r]*b[c];
        }
        __syncthreads();
    }
    float* X = g_xt + (size_t)h*NN + (size_t)i0*NRES + j0;
    #pragma unroll
    for (int r=0;r<8;++r){
        float4* p = (float4*)(X + (size_t)(ty*8+r)*NRES + tx*8);
        p[0] = make_float4(acc[r][0],acc[r][1],acc[r][2],acc[r][3]);
        p[1] = make_float4(acc[r][4],acc[r][5],acc[r][6],acc[r][7]);
    }
}

// ---- LN over h + output GEMM + gate; 64 rows/block ----
__global__ __launch_bounds__(256)
void out_kernel(const float* __restrict__ low, const float* __restrict__ lob,
                const float* __restrict__ zb, float* __restrict__ out)
{
    __shared__ float xs[128*66];
    __shared__ float zw_s[16*132];
    __shared__ float mu_s[64], rs_s[64];
    __shared__ float low_s[128], lob_s[128];
    int tid=threadIdx.x;
    int row0 = blockIdx.x*64;
    if (tid<128){ low_s[tid]=low[tid]; lob_s[tid]=lob[tid]; }
    #pragma unroll
    for (int it=0; it<32; ++it){
        int f = tid + it*256;
        int r = f&63, h = f>>6;
        xs[h*66 + r] = g_xt[(size_t)h*NN + row0 + r];
    }
    __syncthreads();
    int lane=tid&31, wid=tid>>5;
    #pragma unroll
    for (int rr=0;rr<8;++rr){
        int r = wid*8+rr;
        float s=0.f,q=0.f;
        #pragma unroll
        for (int m=0;m<4;++m){ float x=xs[(lane+32*m)*66 + r]; s+=x; q+=x*x; }
        #pragma unroll
        for (int o=16;o>0;o>>=1){ s+=__shfl_xor_sync(0xffffffffu,s,o); q+=__shfl_xor_sync(0xffffffffu,q,o); }
        if (lane==0){
            float mu=s*(1.f/128.f), var=q*(1.f/128.f)-mu*mu;
            mu_s[r]=mu; rs_s[r]=rsqrtf(fmaxf(var,0.f)+EPSF);
        }
    }
    __syncthreads();
    int tx=tid&15, ty=tid>>4;
    float acc[4][8];
    #pragma unroll
    for (int u=0;u<4;++u)
        #pragma unroll
        for (int v=0;v<8;++v) acc[u][v]=0.f;
    float mu[4], rs[4];
    #pragma unroll
    for (int u=0;u<4;++u){ mu[u]=mu_s[ty*4+u]; rs[u]=rs_s[ty*4+u]; }
    const float* zwT = g_wT + 5*CH*CH;

    for (int h0=0;h0<CH;h0+=16){
        #pragma unroll
        for (int it=0; it<2; ++it){
            int f=tid+it*256;
            int hh=f>>5, o4=f&31;
            *(float4*)(zw_s + hh*132 + o4*4) = *(const float4*)(zwT + (h0+hh)*CH + o4*4);
        }
        __syncthreads();
        #pragma unroll
        for (int hh=0; hh<16; ++hh){
            int h=h0+hh;
            float lw=low_s[h], lb=lob_s[h];
            float xn[4];
            #pragma unroll
            for (int u=0;u<4;++u) xn[u] = (xs[h*66 + ty*4+u]-mu[u])*rs[u]*lw + lb;
            float w[8];
            *(float4*)(w)   = *(float4*)(zw_s + hh*132 + tx*8);
            *(float4*)(w+4) = *(float4*)(zw_s + hh*132 + tx*8 + 4);
            #pragma unroll
            for (int u=0;u<4;++u)
                #pragma unroll
                for (int v=0;v<8;++v) acc[u][v] += xn[u]*w[v];
        }
        __syncthreads();
    }
    #pragma unroll
    for (int u=0;u<4;++u){
        int grow=row0+ty*4+u;
        const float4* g4 = (const float4*)(g_gate + (size_t)grow*CH + tx*8);
        const float4* b4 = (const float4*)(zb + tx*8);
        float4* o4p = (float4*)(out + (size_t)grow*CH + tx*8);
        #pragma unroll
        for (int w2=0;w2<2;++w2){
            float4 g=g4[w2], b=b4[w2];
            o4p[w2] = make_float4(g.x*(acc[u][w2*4+0]+b.x),
                                  g.y*(acc[u][w2*4+1]+b.y),
                                  g.z*(acc[u][w2*4+2]+b.z),
                                  g.w*(acc[u][w2*4+3]+b.w));
        }
    }
}

extern "C" void kernel_launch(void* const* d_in, const int* in_sizes, int n_in,
                              void* d_out, int out_size) {
    const float* z      = (const float*)d_in[0];
    const float* mask   = (const float*)d_in[1];
    const float* ln_in_w= (const float*)d_in[2];
    const float* ln_in_b= (const float*)d_in[3];
    const float* a_g_w  = (const float*)d_in[4];
    const float* a_g_b  = (const float*)d_in[5];
    const float* a_p_w  = (const float*)d_in[6];
    const float* a_p_b  = (const float*)d_in[7];
    const float* b_g_w  = (const float*)d_in[8];
    const float* b_g_b  = (const float*)d_in[9];
    const float* b_p_w  = (const float*)d_in[10];
    const float* b_p_b  = (const float*)d_in[11];
    const float* g_w    = (const float*)d_in[12];
    const float* g_b    = (const float*)d_in[13];
    const float* ln_out_w=(const float*)d_in[14];
    const float* ln_out_b=(const float*)d_in[15];
    const float* z_w    = (const float*)d_in[16];
    const float* z_b    = (const float*)d_in[17];
    float* out = (float*)d_out;

    dim3 tb(32,8), tg(4,4);
    transpose128<<<tg,tb>>>(a_g_w,0);
    transpose128<<<tg,tb>>>(a_p_w,1);
    transpose128<<<tg,tb>>>(b_g_w,2);
    transpose128<<<tg,tb>>>(b_p_w,3);
    transpose128<<<tg,tb>>>(g_w,4);
    transpose128<<<tg,tb>>>(z_w,5);

    proj_kernel<<<NN/32,256>>>(z, mask, ln_in_w, ln_in_b,
                               a_g_b, a_p_b, b_g_b, b_p_b, g_b);
    tri_kernel<<<dim3(3,3,128),256>>>();
    out_kernel<<<NN/64,256>>>(ln_out_w, ln_out_b, z_b, out);
}